// round 5
// baseline (speedup 1.0000x reference)
#include <cuda_runtime.h>

#define NLV 14
#define TMASK ((1u << 19) - 1u)
#define PR1 2654435761u
#define PR2 805459861u

typedef unsigned long long u64;

__device__ __forceinline__ u64 pk2(float a, float b) {
    u64 r; asm("mov.b64 %0, {%1, %2};" : "=l"(r) : "f"(a), "f"(b)); return r;
}
__device__ __forceinline__ void upk2(u64 p, float& a, float& b) {
    asm("mov.b64 {%0, %1}, %2;" : "=f"(a), "=f"(b) : "l"(p));
}
__device__ __forceinline__ u64 ffma2(u64 a, u64 b, u64 c) {
    u64 d; asm("fma.rn.f32x2 %0, %1, %2, %3;" : "=l"(d) : "l"(a), "l"(b), "l"(c)); return d;
}
__device__ __forceinline__ float tanha(float x) {
    float y; asm("tanh.approx.f32 %0, %1;" : "=f"(y) : "f"(x)); return y;
}

__global__ void __launch_bounds__(128, 3)
deformnet_kernel(const float* __restrict__ x, const float* __restrict__ e,
                 const float* __restrict__ tables,
                 const float* __restrict__ W1, const float* __restrict__ b1,
                 const float* __restrict__ W2, const float* __restrict__ b2,
                 const float* __restrict__ W3, const float* __restrict__ b3,
                 const float* __restrict__ bbox,
                 float* __restrict__ out, int n)
{
    __shared__ __align__(16) float sW1[36 * 64];
    __shared__ __align__(16) float sW2[64 * 64];
    __shared__ __align__(16) float sW3[64 * 4];
    __shared__ __align__(16) float sb1[64];
    __shared__ __align__(16) float sb2[64];
    __shared__ float sb3[3];
    __shared__ float sbb[6];

    const int tid = threadIdx.x;
    for (int i = tid; i < 36 * 64; i += 128) sW1[i] = W1[i];
    for (int i = tid; i < 64 * 64; i += 128) sW2[i] = W2[i];
    if (tid < 64) {
        sb1[tid] = b1[tid];
        sb2[tid] = b2[tid];
        sW3[tid * 4 + 0] = W3[tid * 3 + 0];
        sW3[tid * 4 + 1] = W3[tid * 3 + 1];
        sW3[tid * 4 + 2] = W3[tid * 3 + 2];
        sW3[tid * 4 + 3] = 0.0f;
    }
    if (tid < 3) sb3[tid] = b3[tid];
    if (tid < 6) sbb[tid] = bbox[tid];
    __syncthreads();

    const int idx = blockIdx.x * 128 + tid;
    if (idx >= n) return;

    const float lo0 = sbb[0], lo1 = sbb[1], lo2 = sbb[2];
    const float s0 = sbb[3] - lo0, s1 = sbb[4] - lo1, s2 = sbb[5] - lo2;
    const float xr0 = x[idx * 3 + 0];
    const float xr1 = x[idx * 3 + 1];
    const float xr2 = x[idx * 3 + 2];
    const float xn0 = (xr0 - lo0) / s0;
    const float xn1 = (xr1 - lo1) / s1;
    const float xn2 = (xr2 - lo2) / s2;

    // ------------------------------------------------------------------
    // Hash-grid encode: 14 levels, 8 corners each, smoothstep trilinear.
    // Tables fit in L2 (58.7MB); gathers are 8B (float2) random loads.
    // ------------------------------------------------------------------
    float fin[36];
    const u64* __restrict__ tab = (const u64*)tables;
    const float RESF[NLV] = {16.f, 21.f, 27.f, 36.f, 48.f, 64.f, 84.f,
                             111.f, 147.f, 194.f, 256.f, 339.f, 447.f, 590.f};

#pragma unroll
    for (int l = 0; l < NLV; l++) {
        const float r = RESF[l];
        float p0 = xn0 * r, p1 = xn1 * r, p2 = xn2 * r;
        float g0 = floorf(p0), g1 = floorf(p1), g2 = floorf(p2);
        float f0 = p0 - g0, f1 = p1 - g1, f2 = p2 - g2;
        // smoothstep weights
        float wa = f0 * f0 * (3.0f - 2.0f * f0);
        float wb = f1 * f1 * (3.0f - 2.0f * f1);
        float wc = f2 * f2 * (3.0f - 2.0f * f2);
        unsigned B0 = (unsigned)g0, B1 = (unsigned)g1, B2 = (unsigned)g2;
        unsigned X0 = B0, X1 = B0 + 1u;
        unsigned Y0 = B1 * PR1, Y1 = Y0 + PR1;
        unsigned Z0 = B2 * PR2, Z1 = Z0 + PR2;
        const u64* tl = tab + ((size_t)l << 19);
        // issue all 8 gathers up front for MLP=8 per level
        u64 v000 = __ldg(tl + ((X0 ^ Y0 ^ Z0) & TMASK));
        u64 v001 = __ldg(tl + ((X0 ^ Y0 ^ Z1) & TMASK));
        u64 v010 = __ldg(tl + ((X0 ^ Y1 ^ Z0) & TMASK));
        u64 v011 = __ldg(tl + ((X0 ^ Y1 ^ Z1) & TMASK));
        u64 v100 = __ldg(tl + ((X1 ^ Y0 ^ Z0) & TMASK));
        u64 v101 = __ldg(tl + ((X1 ^ Y0 ^ Z1) & TMASK));
        u64 v110 = __ldg(tl + ((X1 ^ Y1 ^ Z0) & TMASK));
        u64 v111 = __ldg(tl + ((X1 ^ Y1 ^ Z1) & TMASK));
        float ua = 1.0f - wa, ub = 1.0f - wb, uc = 1.0f - wc;
        float m00 = ub * uc, m01 = ub * wc, m10 = wb * uc, m11 = wb * wc;
        float w000 = ua * m00, w001 = ua * m01, w010 = ua * m10, w011 = ua * m11;
        float w100 = wa * m00, w101 = wa * m01, w110 = wa * m10, w111 = wa * m11;
        u64 acc = ffma2(pk2(w000, w000), v000, 0ull);
        acc = ffma2(pk2(w001, w001), v001, acc);
        acc = ffma2(pk2(w010, w010), v010, acc);
        acc = ffma2(pk2(w011, w011), v011, acc);
        acc = ffma2(pk2(w100, w100), v100, acc);
        acc = ffma2(pk2(w101, w101), v101, acc);
        acc = ffma2(pk2(w110, w110), v110, acc);
        acc = ffma2(pk2(w111, w111), v111, acc);
        upk2(acc, fin[2 * l], fin[2 * l + 1]);
    }

    // extra features e[idx, 0:8]  (row is 32B aligned)
    {
        const float4* e4 = (const float4*)e;
        float4 ea = __ldg(e4 + idx * 2);
        float4 eb = __ldg(e4 + idx * 2 + 1);
        fin[28] = ea.x; fin[29] = ea.y; fin[30] = ea.z; fin[31] = ea.w;
        fin[32] = eb.x; fin[33] = eb.y; fin[34] = eb.z; fin[35] = eb.w;
    }

    // ------------------------------------------------------------------
    // Layer 1: 36 -> 64, packed f32x2 (neuron pairs), weights via LDS.128
    // ------------------------------------------------------------------
    u64 h1[32];
    {
        const u64* sb1u = (const u64*)sb1;
#pragma unroll
        for (int j = 0; j < 32; j++) h1[j] = sb1u[j];
        const ulonglong2* w1q = (const ulonglong2*)sW1;  // 16 per row of 64 floats
#pragma unroll
        for (int i = 0; i < 36; i++) {
            u64 xi = pk2(fin[i], fin[i]);
            const ulonglong2* row = w1q + i * 16;
#pragma unroll
            for (int q = 0; q < 16; q++) {
                ulonglong2 w = row[q];
                h1[2 * q]     = ffma2(xi, w.x, h1[2 * q]);
                h1[2 * q + 1] = ffma2(xi, w.y, h1[2 * q + 1]);
            }
        }
        // tanh in place
#pragma unroll
        for (int j = 0; j < 32; j++) {
            float a, b; upk2(h1[j], a, b);
            h1[j] = pk2(tanha(a), tanha(b));
        }
    }

    // ------------------------------------------------------------------
    // Layer 2 (64->64) split into two 32-column halves to cap registers,
    // each half immediately consumed by layer 3 (64->3).
    // ------------------------------------------------------------------
    float o0 = sb3[0], o1 = sb3[1], o2 = sb3[2];
    {
        const ulonglong2* w2q = (const ulonglong2*)sW2;  // 16 per row
        const float4* w3q = (const float4*)sW3;          // padded [64][4]
        const u64* sb2u = (const u64*)sb2;
#pragma unroll
        for (int half = 0; half < 2; half++) {
            u64 h2[16];
#pragma unroll
            for (int q = 0; q < 16; q++) h2[q] = sb2u[half * 16 + q];
#pragma unroll
            for (int ip = 0; ip < 32; ip++) {
                float a, b; upk2(h1[ip], a, b);
                u64 xa = pk2(a, a);
                u64 xb = pk2(b, b);
                const ulonglong2* r0 = w2q + (2 * ip) * 16 + half * 8;
                const ulonglong2* r1 = r0 + 16;
#pragma unroll
                for (int q = 0; q < 8; q++) {
                    ulonglong2 wA = r0[q];
                    ulonglong2 wB = r1[q];
                    h2[2 * q]     = ffma2(xa, wA.x, h2[2 * q]);
                    h2[2 * q + 1] = ffma2(xa, wA.y, h2[2 * q + 1]);
                    h2[2 * q]     = ffma2(xb, wB.x, h2[2 * q]);
                    h2[2 * q + 1] = ffma2(xb, wB.y, h2[2 * q + 1]);
                }
            }
            // tanh + layer 3 partial
#pragma unroll
            for (int q = 0; q < 16; q++) {
                float a, b; upk2(h2[q], a, b);
                float ta = tanha(a), tb = tanha(b);
                int j = half * 32 + 2 * q;
                float4 wA = w3q[j];
                float4 wB = w3q[j + 1];
                o0 = fmaf(ta, wA.x, o0); o0 = fmaf(tb, wB.x, o0);
                o1 = fmaf(ta, wA.y, o1); o1 = fmaf(tb, wB.y, o1);
                o2 = fmaf(ta, wA.z, o2); o2 = fmaf(tb, wB.z, o2);
            }
        }
    }

    // residual in normalized space, rescale to bbox
    out[idx * 3 + 0] = (o0 + xn0) * s0 + lo0;
    out[idx * 3 + 1] = (o1 + xn1) * s1 + lo1;
    out[idx * 3 + 2] = (o2 + xn2) * s2 + lo2;
}

extern "C" void kernel_launch(void* const* d_in, const int* in_sizes, int n_in,
                              void* d_out, int out_size) {
    const float* x      = (const float*)d_in[0];
    const float* e      = (const float*)d_in[1];
    const float* tables = (const float*)d_in[2];
    const float* W1     = (const float*)d_in[3];
    const float* b1     = (const float*)d_in[4];
    const float* W2     = (const float*)d_in[5];
    const float* b2     = (const float*)d_in[6];
    const float* W3     = (const float*)d_in[7];
    const float* b3     = (const float*)d_in[8];
    const float* bbox   = (const float*)d_in[9];

    const int n = in_sizes[0] / 3;
    const int bs = 128;
    const int nb = (n + bs - 1) / bs;
    deformnet_kernel<<<nb, bs>>>(x, e, tables, W1, b1, W2, b2, W3, b3, bbox,
                                 (float*)d_out, n);
}